// round 3
// baseline (speedup 1.0000x reference)
#include <cuda_runtime.h>

#define N_NODES 100000
#define E_MAX   3200000
#define NPAD    102400          // padded node count (multiple of 1024)
#define NBLK    98              // NPAD/1024 blocks cover >= N_NODES

// ---------------- device scratch (no allocations allowed) ----------------
__device__ int   g_is64;
__device__ int   g_deg[NPAD];
__device__ int   g_cursor[NPAD];
__device__ int   g_bsum[128];
__device__ int   g_boff[128];
__device__ int   g_rowptr[NPAD + 1];
__device__ float g_invdeg[NPAD];
__device__ int   g_csr[E_MAX];
__device__ float g_agg[(size_t)N_NODES * 128];
__device__ float g_h1 [(size_t)N_NODES * 128];
__device__ float g_h2 [(size_t)N_NODES * 128];
__device__ float g_G  [(size_t)N_NODES * 8];
__device__ float g_R  [(size_t)N_NODES * 8];

// ---------------- f32x2 packed-FMA helpers (sm_103a) ----------------
__device__ __forceinline__ unsigned long long pk2(float a, float b) {
    unsigned long long r;
    asm("mov.b64 %0, {%1, %2};" : "=l"(r) : "f"(a), "f"(b));
    return r;
}
__device__ __forceinline__ float2 upk2(unsigned long long v) {
    float2 r;
    asm("mov.b64 {%0, %1}, %2;" : "=f"(r.x), "=f"(r.y) : "l"(v));
    return r;
}
__device__ __forceinline__ void fma2(unsigned long long& d,
                                     unsigned long long a,
                                     unsigned long long b) {
    asm("fma.rn.f32x2 %0, %1, %2, %0;" : "+l"(d) : "l"(a), "l"(b));
}

// ---------------- edge-index dtype detection (int32 vs int64) ----------------
// int64 little-endian values < 2^17 have zero high 32-bit words; int32 random
// indices in [0, 1e5) at odd positions are essentially never all zero.
__global__ void k_detect(const int* __restrict__ ei) {
    if (threadIdx.x == 0 && blockIdx.x == 0) {
        int acc = 0;
        for (int i = 0; i < 128; i++) acc |= ei[2 * i + 1];
        g_is64 = (acc == 0) ? 1 : 0;
    }
}

__device__ __forceinline__ int load_edge(const void* ei, int is64, size_t idx) {
    return is64 ? (int)((const long long*)ei)[idx] : ((const int*)ei)[idx];
}

// ---------------- CSR build ----------------
__global__ void k_zero() {
    int i = blockIdx.x * blockDim.x + threadIdx.x;
    if (i < NPAD) { g_deg[i] = 0; g_cursor[i] = 0; }
}

__global__ void k_hist(const void* __restrict__ ei, int E) {
    int is64 = g_is64;
    int stride = gridDim.x * blockDim.x;
    for (int i = blockIdx.x * blockDim.x + threadIdx.x; i < E; i += stride) {
        int d = load_edge(ei, is64, (size_t)E + i);
        atomicAdd(&g_deg[d], 1);
    }
}

__global__ void k_reduce() {
    __shared__ int ws[8];
    int t = threadIdx.x, lane = t & 31, warp = t >> 5;
    int4 v = ((const int4*)g_deg)[blockIdx.x * 256 + t];
    int s = v.x + v.y + v.z + v.w;
    #pragma unroll
    for (int off = 16; off; off >>= 1)
        s += __shfl_xor_sync(0xffffffffu, s, off);
    if (lane == 0) ws[warp] = s;
    __syncthreads();
    if (t == 0) {
        int tot = 0;
        #pragma unroll
        for (int i = 0; i < 8; i++) tot += ws[i];
        g_bsum[blockIdx.x] = tot;
    }
}

__global__ void k_scanb(int E) {
    if (threadIdx.x == 0 && blockIdx.x == 0) {
        int run = 0;
        for (int i = 0; i < NBLK; i++) { g_boff[i] = run; run += g_bsum[i]; }
        g_rowptr[N_NODES] = E;
    }
}

__global__ void k_scanw() {
    __shared__ int ws[8];
    int blk = blockIdx.x, t = threadIdx.x;
    int lane = t & 31, warp = t >> 5;
    int4 v = ((const int4*)g_deg)[blk * 256 + t];
    int tsum = v.x + v.y + v.z + v.w;
    int x = tsum;
    #pragma unroll
    for (int off = 1; off < 32; off <<= 1) {
        int y = __shfl_up_sync(0xffffffffu, x, off);
        if (lane >= off) x += y;
    }
    if (lane == 31) ws[warp] = x;
    __syncthreads();
    if (warp == 0) {
        int w = (lane < 8) ? ws[lane] : 0;
        #pragma unroll
        for (int off = 1; off < 8; off <<= 1) {
            int y = __shfl_up_sync(0xffffffffu, w, off);
            if (lane >= off) w += y;
        }
        if (lane < 8) ws[lane] = w;
    }
    __syncthreads();
    int excl = x - tsum + (warp ? ws[warp - 1] : 0) + g_boff[blk];
    int base = blk * 1024 + t * 4;
    int run = excl;
    g_rowptr[base + 0] = run;
    g_invdeg[base + 0] = 1.0f / (float)(v.x > 1 ? v.x : 1);
    run += v.x;
    g_rowptr[base + 1] = run;
    g_invdeg[base + 1] = 1.0f / (float)(v.y > 1 ? v.y : 1);
    run += v.y;
    g_rowptr[base + 2] = run;
    g_invdeg[base + 2] = 1.0f / (float)(v.z > 1 ? v.z : 1);
    run += v.z;
    g_rowptr[base + 3] = run;
    g_invdeg[base + 3] = 1.0f / (float)(v.w > 1 ? v.w : 1);
    run += v.w;
}

__global__ void k_scatter(const void* __restrict__ ei, int E) {
    int is64 = g_is64;
    int stride = gridDim.x * blockDim.x;
    for (int i = blockIdx.x * blockDim.x + threadIdx.x; i < E; i += stride) {
        int s = load_edge(ei, is64, i);
        int d = load_edge(ei, is64, (size_t)E + i);
        int pos = atomicAdd(&g_cursor[d], 1);
        g_csr[g_rowptr[d] + pos] = s;
    }
}

// ---------------- mean aggregation (warp per node, float4 lanes) ----------------
__global__ void k_agg(const float* __restrict__ h, float* __restrict__ o) {
    int gw = (blockIdx.x * blockDim.x + threadIdx.x) >> 5;   // node id
    int lane = threadIdx.x & 31;
    int beg = g_rowptr[gw], end = g_rowptr[gw + 1];
    float4 a0 = make_float4(0.f, 0.f, 0.f, 0.f);
    float4 a1 = make_float4(0.f, 0.f, 0.f, 0.f);
    int e = beg;
    for (; e + 2 <= end; e += 2) {
        int s0 = g_csr[e], s1 = g_csr[e + 1];
        float4 v0 = ((const float4*)(h + (size_t)s0 * 128))[lane];
        float4 v1 = ((const float4*)(h + (size_t)s1 * 128))[lane];
        a0.x += v0.x; a0.y += v0.y; a0.z += v0.z; a0.w += v0.w;
        a1.x += v1.x; a1.y += v1.y; a1.z += v1.z; a1.w += v1.w;
    }
    if (e < end) {
        int s0 = g_csr[e];
        float4 v0 = ((const float4*)(h + (size_t)s0 * 128))[lane];
        a0.x += v0.x; a0.y += v0.y; a0.z += v0.z; a0.w += v0.w;
    }
    float d = g_invdeg[gw];
    float4 r;
    r.x = (a0.x + a1.x) * d;
    r.y = (a0.y + a1.y) * d;
    r.z = (a0.z + a1.z) * d;
    r.w = (a0.w + a1.w) * d;
    ((float4*)(o + (size_t)gw * 128))[lane] = r;
}

// ---------------- fused GEMM: out = relu(agg@Wl^T + h@Wr^T + b) ----------------
// C[N,128] = A[N,256] * B[256,128],  A = [agg | h],  B[k][j] = Wl/Wr[j][k]
// BM=64, BN=128, BK=16, 256 threads, thread tile 8 rows x 4 cols, f32x2 FMAs.
template <int RELU>
__global__ __launch_bounds__(256, 2)
void k_gemm(const float* __restrict__ Ag, const float* __restrict__ Hm,
            const float* __restrict__ Wl, const float* __restrict__ Wr,
            const float* __restrict__ bias, float* __restrict__ out)
{
    __shared__ __align__(16) float As[2][16][66];
    __shared__ __align__(16) float Bs[2][16][132];

    const int tid  = threadIdx.x;
    const int bm0  = blockIdx.x * 64;
    const int warp = tid >> 5, lane = tid & 31;
    const int row0 = (warp & 1) * 32 + (lane & 3) * 8;     // 0..56, step 8
    const int col0 = (warp >> 1) * 32 + (lane >> 2) * 4;   // 0..124, step 4
    const int arow = tid >> 2, akq = tid & 3;
    const int grow = bm0 + arow;
    const bool rok = grow < N_NODES;
    const int bj0 = tid >> 2, bkq = tid & 3;

    float4 ar, br0, br1;

#define GLOAD(kt) {                                                              \
    int gk = (kt) * 16 + akq * 4;                                                \
    if (rok) {                                                                   \
        const float* p = (gk < 128) ? (Ag + (size_t)grow * 128 + gk)             \
                                    : (Hm + (size_t)grow * 128 + (gk - 128));    \
        ar = *(const float4*)p;                                                  \
    } else ar = make_float4(0.f, 0.f, 0.f, 0.f);                                 \
    int gkb = (kt) * 16 + bkq * 4;                                               \
    { const float* p = (gkb < 128) ? (Wl + bj0 * 128 + gkb)                      \
                                   : (Wr + bj0 * 128 + (gkb - 128));             \
      br0 = *(const float4*)p; }                                                 \
    { int bj1 = bj0 + 64;                                                        \
      const float* p = (gkb < 128) ? (Wl + bj1 * 128 + gkb)                      \
                                   : (Wr + bj1 * 128 + (gkb - 128));             \
      br1 = *(const float4*)p; }                                                 \
}
#define SSTORE(s) {                                                              \
    As[s][akq * 4 + 0][arow] = ar.x; As[s][akq * 4 + 1][arow] = ar.y;            \
    As[s][akq * 4 + 2][arow] = ar.z; As[s][akq * 4 + 3][arow] = ar.w;            \
    Bs[s][bkq * 4 + 0][bj0] = br0.x; Bs[s][bkq * 4 + 1][bj0] = br0.y;            \
    Bs[s][bkq * 4 + 2][bj0] = br0.z; Bs[s][bkq * 4 + 3][bj0] = br0.w;            \
    Bs[s][bkq * 4 + 0][bj0 + 64] = br1.x; Bs[s][bkq * 4 + 1][bj0 + 64] = br1.y;  \
    Bs[s][bkq * 4 + 2][bj0 + 64] = br1.z; Bs[s][bkq * 4 + 3][bj0 + 64] = br1.w;  \
}

    unsigned long long acc[4][4];
    #pragma unroll
    for (int p = 0; p < 4; p++)
        #pragma unroll
        for (int j = 0; j < 4; j++) acc[p][j] = 0ull;

    GLOAD(0);
    SSTORE(0);
    __syncthreads();

    #pragma unroll 1
    for (int kt = 0; kt < 16; kt++) {
        int s = kt & 1;
        if (kt < 15) GLOAD(kt + 1);
        #pragma unroll
        for (int kk = 0; kk < 16; kk++) {
            unsigned long long a2[4];
            #pragma unroll
            for (int p = 0; p < 4; p++)
                a2[p] = *(const unsigned long long*)&As[s][kk][row0 + 2 * p];
            float4 b4 = *(const float4*)&Bs[s][kk][col0];
            unsigned long long bb0 = pk2(b4.x, b4.x);
            unsigned long long bb1 = pk2(b4.y, b4.y);
            unsigned long long bb2 = pk2(b4.z, b4.z);
            unsigned long long bb3 = pk2(b4.w, b4.w);
            #pragma unroll
            for (int p = 0; p < 4; p++) {
                fma2(acc[p][0], a2[p], bb0);
                fma2(acc[p][1], a2[p], bb1);
                fma2(acc[p][2], a2[p], bb2);
                fma2(acc[p][3], a2[p], bb3);
            }
        }
        if (kt < 15) { SSTORE(s ^ 1); __syncthreads(); }
    }

    float4 b4 = *(const float4*)&bias[col0];
    #pragma unroll
    for (int p = 0; p < 4; p++) {
        float2 c0 = upk2(acc[p][0]), c1 = upk2(acc[p][1]);
        float2 c2 = upk2(acc[p][2]), c3 = upk2(acc[p][3]);
        float4 lo = make_float4(c0.x + b4.x, c1.x + b4.y, c2.x + b4.z, c3.x + b4.w);
        float4 hi = make_float4(c0.y + b4.x, c1.y + b4.y, c2.y + b4.z, c3.y + b4.w);
        if (RELU) {
            lo.x = fmaxf(lo.x, 0.f); lo.y = fmaxf(lo.y, 0.f);
            lo.z = fmaxf(lo.z, 0.f); lo.w = fmaxf(lo.w, 0.f);
            hi.x = fmaxf(hi.x, 0.f); hi.y = fmaxf(hi.y, 0.f);
            hi.z = fmaxf(hi.z, 0.f); hi.w = fmaxf(hi.w, 0.f);
        }
        int r0 = bm0 + row0 + 2 * p;
        if (r0 < N_NODES)     *(float4*)&out[(size_t)r0 * 128 + col0] = lo;
        if (r0 + 1 < N_NODES) *(float4*)&out[(size_t)(r0 + 1) * 128 + col0] = hi;
    }
#undef GLOAD
#undef SSTORE
}

// ---------------- layer-3 thin projections: G = H2@Wl3^T, R = H2@Wr3^T + b3 ----
__global__ void k_gemm3(const float* __restrict__ H,
                        const float* __restrict__ Wl, const float* __restrict__ Wr,
                        const float* __restrict__ b) {
    __shared__ __align__(16) float sW[12 * 128];
    __shared__ float sb[8];
    int t = threadIdx.x;
    for (int i = t; i < 1536; i += 256) sW[i] = (i < 768) ? Wl[i] : Wr[i - 768];
    if (t < 6) sb[t] = b[t];
    __syncthreads();
    int lane = t & 31, warp = t >> 5;
    int node = blockIdx.x * 8 + warp;
    float4 h4 = ((const float4*)(H + (size_t)node * 128))[lane];
    float r[12];
    #pragma unroll
    for (int j = 0; j < 12; j++) {
        float4 w = ((const float4*)(sW + j * 128))[lane];
        r[j] = h4.x * w.x + h4.y * w.y + h4.z * w.z + h4.w * w.w;
    }
    #pragma unroll
    for (int j = 0; j < 12; j++) {
        #pragma unroll
        for (int off = 16; off; off >>= 1)
            r[j] += __shfl_xor_sync(0xffffffffu, r[j], off);
    }
    if (lane == 0) {
        #pragma unroll
        for (int j = 0; j < 6; j++) {
            g_G[(size_t)node * 8 + j] = r[j];
            g_R[(size_t)node * 8 + j] = r[j + 6] + sb[j];
        }
    }
}

// ---------------- final: out = invdeg * sum_e G[src] + R  (6-dim aggregation) ----
__global__ void k_final(float* __restrict__ out) {
    int gw = (blockIdx.x * blockDim.x + threadIdx.x) >> 5;   // node
    int lane = threadIdx.x & 31;
    int sub = lane >> 3, c = lane & 7;                       // 4 neighbors x 8 lanes
    int beg = g_rowptr[gw], end = g_rowptr[gw + 1];
    float acc = 0.f;
    for (int e = beg + sub; e < end; e += 4) {
        int s = g_csr[e];
        acc += g_G[(size_t)s * 8 + c];
    }
    acc += __shfl_xor_sync(0xffffffffu, acc, 8);
    acc += __shfl_xor_sync(0xffffffffu, acc, 16);
    if (lane < 6)
        out[(size_t)gw * 6 + lane] = acc * g_invdeg[gw] + g_R[(size_t)gw * 8 + lane];
}

// ---------------- host launcher ----------------
extern "C" void kernel_launch(void* const* d_in, const int* in_sizes, int n_in,
                              void* d_out, int out_size) {
    const float* x   = (const float*)d_in[0];
    const void*  ei  = d_in[1];
    const float *Wl1 = (const float*)d_in[2], *Wr1 = (const float*)d_in[3], *b1 = (const float*)d_in[4];
    const float *Wl2 = (const float*)d_in[5], *Wr2 = (const float*)d_in[6], *b2 = (const float*)d_in[7];
    const float *Wl3 = (const float*)d_in[8], *Wr3 = (const float*)d_in[9], *b3 = (const float*)d_in[10];
    float* out = (float*)d_out;
    int E = in_sizes[1] / 2;

    float *agg, *h1, *h2;
    cudaGetSymbolAddress((void**)&agg, g_agg);
    cudaGetSymbolAddress((void**)&h1,  g_h1);
    cudaGetSymbolAddress((void**)&h2,  g_h2);

    // CSR build (counting sort by destination)
    k_detect<<<1, 32>>>((const int*)ei);
    k_zero<<<NPAD / 256, 256>>>();
    k_hist<<<2560, 256>>>(ei, E);
    k_reduce<<<NBLK, 256>>>();
    k_scanb<<<1, 32>>>(E);
    k_scanw<<<NBLK, 256>>>();
    k_scatter<<<2560, 256>>>(ei, E);

    // layer 1
    k_agg<<<N_NODES / 8, 256>>>(x, agg);
    k_gemm<1><<<(N_NODES + 63) / 64, 256>>>(agg, x, Wl1, Wr1, b1, h1);
    // layer 2
    k_agg<<<N_NODES / 8, 256>>>(h1, agg);
    k_gemm<1><<<(N_NODES + 63) / 64, 256>>>(agg, h1, Wl2, Wr2, b2, h2);
    // layer 3 (project to 6 dims first, then aggregate cheap)
    k_gemm3<<<N_NODES / 8, 256>>>(h2, Wl3, Wr3, b3);
    k_final<<<N_NODES / 8, 256>>>(out);
}

// round 4
// speedup vs baseline: 1.0460x; 1.0460x over previous
#include <cuda_runtime.h>
#include <cuda_bf16.h>

#define N_NODES 100000
#define E_MAX   3200000
#define NPAD    102400          // padded node count (multiple of 1024)
#define NBLK    98              // NPAD/1024 blocks cover >= N_NODES

// ---------------- device scratch (no allocations allowed) ----------------
__device__ int   g_is64;
__device__ int   g_deg[NPAD];
__device__ int   g_cursor[NPAD];
__device__ int   g_bsum[128];
__device__ int   g_boff[128];
__device__ int   g_rowptr[NPAD + 1];
__device__ float g_invdeg[NPAD];
__device__ int   g_csr[E_MAX];
__device__ float g_agg[(size_t)N_NODES * 128];
__device__ float g_h1 [(size_t)N_NODES * 128];
__device__ float g_h2 [(size_t)N_NODES * 128];
__device__ __nv_bfloat16 g_xb[(size_t)N_NODES * 128];   // bf16 gather source
__device__ float g_G  [(size_t)N_NODES * 8];
__device__ float g_R  [(size_t)N_NODES * 8];

// ---------------- f32x2 packed-FMA helpers (sm_103a) ----------------
__device__ __forceinline__ unsigned long long pk2(float a, float b) {
    unsigned long long r;
    asm("mov.b64 %0, {%1, %2};" : "=l"(r) : "f"(a), "f"(b));
    return r;
}
__device__ __forceinline__ float2 upk2(unsigned long long v) {
    float2 r;
    asm("mov.b64 {%0, %1}, %2;" : "=f"(r.x), "=f"(r.y) : "l"(v));
    return r;
}
__device__ __forceinline__ void fma2(unsigned long long& d,
                                     unsigned long long a,
                                     unsigned long long b) {
    asm("fma.rn.f32x2 %0, %1, %2, %0;" : "+l"(d) : "l"(a), "l"(b));
}

// ---------------- edge-index dtype detection (int32 vs int64) ----------------
__global__ void k_detect(const int* __restrict__ ei) {
    if (threadIdx.x == 0 && blockIdx.x == 0) {
        int acc = 0;
        for (int i = 0; i < 128; i++) acc |= ei[2 * i + 1];
        g_is64 = (acc == 0) ? 1 : 0;
    }
}

__device__ __forceinline__ int load_edge(const void* ei, int is64, size_t idx) {
    return is64 ? (int)((const long long*)ei)[idx] : ((const int*)ei)[idx];
}

// ---------------- CSR build ----------------
__global__ void k_zero() {
    int i = blockIdx.x * blockDim.x + threadIdx.x;
    if (i < NPAD) g_deg[i] = 0;
}

__global__ void k_hist(const void* __restrict__ ei, int E) {
    int is64 = g_is64;
    int stride = gridDim.x * blockDim.x;
    for (int i = blockIdx.x * blockDim.x + threadIdx.x; i < E; i += stride) {
        int d = load_edge(ei, is64, (size_t)E + i);
        atomicAdd(&g_deg[d], 1);
    }
}

__global__ void k_reduce() {
    __shared__ int ws[8];
    int t = threadIdx.x, lane = t & 31, warp = t >> 5;
    int4 v = ((const int4*)g_deg)[blockIdx.x * 256 + t];
    int s = v.x + v.y + v.z + v.w;
    #pragma unroll
    for (int off = 16; off; off >>= 1)
        s += __shfl_xor_sync(0xffffffffu, s, off);
    if (lane == 0) ws[warp] = s;
    __syncthreads();
    if (t == 0) {
        int tot = 0;
        #pragma unroll
        for (int i = 0; i < 8; i++) tot += ws[i];
        g_bsum[blockIdx.x] = tot;
    }
}

// parallel scan of the NBLK block sums (one 128-thread block)
__global__ void k_scanb(int E) {
    __shared__ int ws[4];
    int t = threadIdx.x;            // 0..127
    int lane = t & 31, warp = t >> 5;
    int v = (t < NBLK) ? g_bsum[t] : 0;
    int x = v;
    #pragma unroll
    for (int off = 1; off < 32; off <<= 1) {
        int y = __shfl_up_sync(0xffffffffu, x, off);
        if (lane >= off) x += y;
    }
    if (lane == 31) ws[warp] = x;
    __syncthreads();
    if (t == 0) {
        int r = 0;
        #pragma unroll
        for (int i = 0; i < 4; i++) { int tmp = ws[i]; ws[i] = r; r += tmp; }
    }
    __syncthreads();
    int excl = x - v + ws[warp];
    if (t < NBLK) g_boff[t] = excl;
    if (t == 0) g_rowptr[N_NODES] = E;
}

__global__ void k_scanw() {
    __shared__ int ws[8];
    int blk = blockIdx.x, t = threadIdx.x;
    int lane = t & 31, warp = t >> 5;
    int4 v = ((const int4*)g_deg)[blk * 256 + t];
    int tsum = v.x + v.y + v.z + v.w;
    int x = tsum;
    #pragma unroll
    for (int off = 1; off < 32; off <<= 1) {
        int y = __shfl_up_sync(0xffffffffu, x, off);
        if (lane >= off) x += y;
    }
    if (lane == 31) ws[warp] = x;
    __syncthreads();
    if (warp == 0) {
        int w = (lane < 8) ? ws[lane] : 0;
        #pragma unroll
        for (int off = 1; off < 8; off <<= 1) {
            int y = __shfl_up_sync(0xffffffffu, w, off);
            if (lane >= off) w += y;
        }
        if (lane < 8) ws[lane] = w;
    }
    __syncthreads();
    int excl = x - tsum + (warp ? ws[warp - 1] : 0) + g_boff[blk];
    int base = blk * 1024 + t * 4;
    int run = excl;
    g_rowptr[base + 0] = run; g_cursor[base + 0] = run;
    g_invdeg[base + 0] = 1.0f / (float)(v.x > 1 ? v.x : 1);
    run += v.x;
    g_rowptr[base + 1] = run; g_cursor[base + 1] = run;
    g_invdeg[base + 1] = 1.0f / (float)(v.y > 1 ? v.y : 1);
    run += v.y;
    g_rowptr[base + 2] = run; g_cursor[base + 2] = run;
    g_invdeg[base + 2] = 1.0f / (float)(v.z > 1 ? v.z : 1);
    run += v.z;
    g_rowptr[base + 3] = run; g_cursor[base + 3] = run;
    g_invdeg[base + 3] = 1.0f / (float)(v.w > 1 ? v.w : 1);
    run += v.w;
}

__global__ void k_scatter(const void* __restrict__ ei, int E) {
    int is64 = g_is64;
    int stride = gridDim.x * blockDim.x;
    for (int i = blockIdx.x * blockDim.x + threadIdx.x; i < E; i += stride) {
        int s = load_edge(ei, is64, i);
        int d = load_edge(ei, is64, (size_t)E + i);
        int pos = atomicAdd(&g_cursor[d], 1);
        g_csr[pos] = s;
    }
}

// ---------------- fp32 -> bf16 feature conversion ----------------
__global__ void k_cvt(const float* __restrict__ in) {
    size_t i = (size_t)blockIdx.x * 256 + threadIdx.x;   // float4 index
    float4 v = ((const float4*)in)[i];
    __nv_bfloat162 a = __floats2bfloat162_rn(v.x, v.y);
    __nv_bfloat162 b = __floats2bfloat162_rn(v.z, v.w);
    uint2 u;
    u.x = *(unsigned*)&a;
    u.y = *(unsigned*)&b;
    ((uint2*)g_xb)[i] = u;
}

// ---------------- mean aggregation from bf16 rows (warp per node) ----------------
__global__ void k_agg_bf(float* __restrict__ o) {
    int gw = (blockIdx.x * blockDim.x + threadIdx.x) >> 5;   // node id
    int lane = threadIdx.x & 31;
    int beg = g_rowptr[gw], end = g_rowptr[gw + 1];
    const __nv_bfloat16* hb = g_xb;
    float4 a0 = make_float4(0.f, 0.f, 0.f, 0.f);
    float4 a1 = make_float4(0.f, 0.f, 0.f, 0.f);
    int e = beg;
    for (; e + 2 <= end; e += 2) {
        int s0 = g_csr[e], s1 = g_csr[e + 1];
        uint2 p0 = ((const uint2*)(hb + (size_t)s0 * 128))[lane];
        uint2 p1 = ((const uint2*)(hb + (size_t)s1 * 128))[lane];
        float2 f;
        f = __bfloat1622float2(*(__nv_bfloat162*)&p0.x); a0.x += f.x; a0.y += f.y;
        f = __bfloat1622float2(*(__nv_bfloat162*)&p0.y); a0.z += f.x; a0.w += f.y;
        f = __bfloat1622float2(*(__nv_bfloat162*)&p1.x); a1.x += f.x; a1.y += f.y;
        f = __bfloat1622float2(*(__nv_bfloat162*)&p1.y); a1.z += f.x; a1.w += f.y;
    }
    if (e < end) {
        int s0 = g_csr[e];
        uint2 p0 = ((const uint2*)(hb + (size_t)s0 * 128))[lane];
        float2 f;
        f = __bfloat1622float2(*(__nv_bfloat162*)&p0.x); a0.x += f.x; a0.y += f.y;
        f = __bfloat1622float2(*(__nv_bfloat162*)&p0.y); a0.z += f.x; a0.w += f.y;
    }
    float d = g_invdeg[gw];
    float4 r;
    r.x = (a0.x + a1.x) * d;
    r.y = (a0.y + a1.y) * d;
    r.z = (a0.z + a1.z) * d;
    r.w = (a0.w + a1.w) * d;
    ((float4*)(o + (size_t)gw * 128))[lane] = r;
}

// ---------------- fused GEMM: out = relu(agg@Wl^T + h@Wr^T + b) ----------------
// C[N,128] = A[N,256] * B[256,128],  A = [agg | h],  B[k][j] = Wl/Wr[j][k]
// BM=64, BN=128, BK=16, 256 threads, thread tile 8 rows x 4 cols, f32x2 FMAs.
// WB: also emit bf16 copy of the output into g_xb (gather source for next layer).
template <int RELU, int WB>
__global__ __launch_bounds__(256, 2)
void k_gemm(const float* __restrict__ Ag, const float* __restrict__ Hm,
            const float* __restrict__ Wl, const float* __restrict__ Wr,
            const float* __restrict__ bias, float* __restrict__ out)
{
    __shared__ __align__(16) float As[2][16][66];
    __shared__ __align__(16) float Bs[2][16][132];

    const int tid  = threadIdx.x;
    const int bm0  = blockIdx.x * 64;
    const int warp = tid >> 5, lane = tid & 31;
    const int row0 = (warp & 1) * 32 + (lane & 3) * 8;     // 0..56, step 8
    const int col0 = (warp >> 1) * 32 + (lane >> 2) * 4;   // 0..124, step 4
    const int arow = tid >> 2, akq = tid & 3;
    const int grow = bm0 + arow;
    const bool rok = grow < N_NODES;
    const int bj0 = tid >> 2, bkq = tid & 3;

    float4 ar, br0, br1;

#define GLOAD(kt) {                                                              \
    int gk = (kt) * 16 + akq * 4;                                                \
    if (rok) {                                                                   \
        const float* p = (gk < 128) ? (Ag + (size_t)grow * 128 + gk)             \
                                    : (Hm + (size_t)grow * 128 + (gk - 128));    \
        ar = *(const float4*)p;                                                  \
    } else ar = make_float4(0.f, 0.f, 0.f, 0.f);                                 \
    int gkb = (kt) * 16 + bkq * 4;                                               \
    { const float* p = (gkb < 128) ? (Wl + bj0 * 128 + gkb)                      \
                                   : (Wr + bj0 * 128 + (gkb - 128));             \
      br0 = *(const float4*)p; }                                                 \
    { int bj1 = bj0 + 64;                                                        \
      const float* p = (gkb < 128) ? (Wl + bj1 * 128 + gkb)                      \
                                   : (Wr + bj1 * 128 + (gkb - 128));             \
      br1 = *(const float4*)p; }                                                 \
}
#define SSTORE(s) {                                                              \
    As[s][akq * 4 + 0][arow] = ar.x; As[s][akq * 4 + 1][arow] = ar.y;            \
    As[s][akq * 4 + 2][arow] = ar.z; As[s][akq * 4 + 3][arow] = ar.w;            \
    Bs[s][bkq * 4 + 0][bj0] = br0.x; Bs[s][bkq * 4 + 1][bj0] = br0.y;            \
    Bs[s][bkq * 4 + 2][bj0] = br0.z; Bs[s][bkq * 4 + 3][bj0] = br0.w;            \
    Bs[s][bkq * 4 + 0][bj0 + 64] = br1.x; Bs[s][bkq * 4 + 1][bj0 + 64] = br1.y;  \
    Bs[s][bkq * 4 + 2][bj0 + 64] = br1.z; Bs[s][bkq * 4 + 3][bj0 + 64] = br1.w;  \
}

    unsigned long long acc[4][4];
    #pragma unroll
    for (int p = 0; p < 4; p++)
        #pragma unroll
        for (int j = 0; j < 4; j++) acc[p][j] = 0ull;

    GLOAD(0);
    SSTORE(0);
    __syncthreads();

    #pragma unroll 1
    for (int kt = 0; kt < 16; kt++) {
        int s = kt & 1;
        if (kt < 15) GLOAD(kt + 1);
        #pragma unroll
        for (int kk = 0; kk < 16; kk++) {
            unsigned long long a2[4];
            #pragma unroll
            for (int p = 0; p < 4; p++)
                a2[p] = *(const unsigned long long*)&As[s][kk][row0 + 2 * p];
            float4 b4 = *(const float4*)&Bs[s][kk][col0];
            unsigned long long bb0 = pk2(b4.x, b4.x);
            unsigned long long bb1 = pk2(b4.y, b4.y);
            unsigned long long bb2 = pk2(b4.z, b4.z);
            unsigned long long bb3 = pk2(b4.w, b4.w);
            #pragma unroll
            for (int p = 0; p < 4; p++) {
                fma2(acc[p][0], a2[p], bb0);
                fma2(acc[p][1], a2[p], bb1);
                fma2(acc[p][2], a2[p], bb2);
                fma2(acc[p][3], a2[p], bb3);
            }
        }
        if (kt < 15) { SSTORE(s ^ 1); __syncthreads(); }
    }

    float4 b4 = *(const float4*)&bias[col0];
    #pragma unroll
    for (int p = 0; p < 4; p++) {
        float2 c0 = upk2(acc[p][0]), c1 = upk2(acc[p][1]);
        float2 c2 = upk2(acc[p][2]), c3 = upk2(acc[p][3]);
        float4 lo = make_float4(c0.x + b4.x, c1.x + b4.y, c2.x + b4.z, c3.x + b4.w);
        float4 hi = make_float4(c0.y + b4.x, c1.y + b4.y, c2.y + b4.z, c3.y + b4.w);
        if (RELU) {
            lo.x = fmaxf(lo.x, 0.f); lo.y = fmaxf(lo.y, 0.f);
            lo.z = fmaxf(lo.z, 0.f); lo.w = fmaxf(lo.w, 0.f);
            hi.x = fmaxf(hi.x, 0.f); hi.y = fmaxf(hi.y, 0.f);
            hi.z = fmaxf(hi.z, 0.f); hi.w = fmaxf(hi.w, 0.f);
        }
        int r0 = bm0 + row0 + 2 * p;
        if (r0 < N_NODES) {
            *(float4*)&out[(size_t)r0 * 128 + col0] = lo;
            if (WB) {
                __nv_bfloat162 q0 = __floats2bfloat162_rn(lo.x, lo.y);
                __nv_bfloat162 q1 = __floats2bfloat162_rn(lo.z, lo.w);
                uint2 u; u.x = *(unsigned*)&q0; u.y = *(unsigned*)&q1;
                *(uint2*)&g_xb[(size_t)r0 * 128 + col0] = u;
            }
        }
        if (r0 + 1 < N_NODES) {
            *(float4*)&out[(size_t)(r0 + 1) * 128 + col0] = hi;
            if (WB) {
                __nv_bfloat162 q0 = __floats2bfloat162_rn(hi.x, hi.y);
                __nv_bfloat162 q1 = __floats2bfloat162_rn(hi.z, hi.w);
                uint2 u; u.x = *(unsigned*)&q0; u.y = *(unsigned*)&q1;
                *(uint2*)&g_xb[(size_t)(r0 + 1) * 128 + col0] = u;
            }
        }
    }
#undef GLOAD
#undef SSTORE
}

// ---------------- layer-3 thin projections: G = H2@Wl3^T, R = H2@Wr3^T + b3 ----
__global__ void k_gemm3(const float* __restrict__ H,
                        const float* __restrict__ Wl, const float* __restrict__ Wr,
                        const float* __restrict__ b) {
    __shared__ __align__(16) float sW[12 * 128];
    __shared__ float sb[8];
    int t = threadIdx.x;
    for (int i = t; i < 1536; i += 256) sW[i] = (i < 768) ? Wl[i] : Wr[i - 768];
    if (t < 6) sb[t] = b[t];
    __syncthreads();
    int lane = t & 31, warp = t >> 5;
    int node = blockIdx.x * 8 + warp;
    float4 h4 = ((const float4*)(H + (size_t)node * 128))[lane];
    float r[12];
    #pragma unroll
    for (int j = 0; j < 12; j++) {
        float4 w = ((const float4*)(sW + j * 128))[lane];
        r[j] = h4.x * w.x + h4.y * w.y + h4.z * w.z + h4.w * w.w;
    }
    #pragma unroll
    for (int j = 0; j < 12; j++) {
        #pragma unroll
        for (int off = 16; off; off >>= 1)
            r[j] += __shfl_xor_sync(0xffffffffu, r[j], off);
    }
    if (lane == 0) {
        #pragma unroll
        for (int j = 0; j < 6; j++) {
            g_G[(size_t)node * 8 + j] = r[j];
            g_R[(size_t)node * 8 + j] = r[j + 6] + sb[j];
        }
    }
}

// ---------------- final: out = invdeg * sum_e G[src] + R  (6-dim aggregation) ----
__global__ void k_final(float* __restrict__ out) {
    int gw = (blockIdx.x * blockDim.x + threadIdx.x) >> 5;   // node
    int lane = threadIdx.x & 31;
    int sub = lane >> 3, c = lane & 7;                       // 4 neighbors x 8 lanes
    int beg = g_rowptr[gw], end = g_rowptr[gw + 1];
    float acc = 0.f;
    for (int e = beg + sub; e < end; e += 4) {
        int s = g_csr[e];
        acc += g_G[(size_t)s * 8 + c];
    }
    acc += __shfl_xor_sync(0xffffffffu, acc, 8);
    acc += __shfl_xor_sync(0xffffffffu, acc, 16);
    if (lane < 6)
        out[(size_t)gw * 6 + lane] = acc * g_invdeg[gw] + g_R[(size_t)gw * 8 + lane];
}

// ---------------- host launcher ----------------
extern "C" void kernel_launch(void* const* d_in, const int* in_sizes, int n_in,
                              void* d_out, int out_size) {
    const float* x   = (const float*)d_in[0];
    const void*  ei  = d_in[1];
    const float *Wl1 = (const float*)d_in[2], *Wr1 = (const float*)d_in[3], *b1 = (const float*)d_in[4];
    const float *Wl2 = (const float*)d_in[5], *Wr2 = (const float*)d_in[6], *b2 = (const float*)d_in[7];
    const float *Wl3 = (const float*)d_in[8], *Wr3 = (const float*)d_in[9], *b3 = (const float*)d_in[10];
    float* out = (float*)d_out;
    int E = in_sizes[1] / 2;

    float *agg, *h1, *h2;
    cudaGetSymbolAddress((void**)&agg, g_agg);
    cudaGetSymbolAddress((void**)&h1,  g_h1);
    cudaGetSymbolAddress((void**)&h2,  g_h2);

    // CSR build (counting sort by destination)
    k_detect<<<1, 32>>>((const int*)ei);
    k_zero<<<NPAD / 256, 256>>>();
    k_hist<<<2560, 256>>>(ei, E);
    k_reduce<<<NBLK, 256>>>();
    k_scanb<<<1, 128>>>(E);
    k_scanw<<<NBLK, 256>>>();
    k_scatter<<<2560, 256>>>(ei, E);
    k_cvt<<<(N_NODES * 128 / 4) / 256, 256>>>(x);   // x -> bf16

    // layer 1 (gemm epilogue emits bf16 h1 into g_xb)
    k_agg_bf<<<N_NODES / 8, 256>>>(agg);
    k_gemm<1, 1><<<(N_NODES + 63) / 64, 256>>>(agg, x, Wl1, Wr1, b1, h1);
    // layer 2
    k_agg_bf<<<N_NODES / 8, 256>>>(agg);
    k_gemm<1, 0><<<(N_NODES + 63) / 64, 256>>>(agg, h1, Wl2, Wr2, b2, h2);
    // layer 3 (project to 6 dims first, then aggregate cheap)
    k_gemm3<<<N_NODES / 8, 256>>>(h2, Wl3, Wr3, b3);
    k_final<<<N_NODES / 8, 256>>>(out);
}

// round 6
// speedup vs baseline: 1.0714x; 1.0243x over previous
#include <cuda_runtime.h>
#include <cuda_bf16.h>

#define N_NODES 100000
#define E_MAX   3200000
#define NPAD    102400          // padded node count (multiple of 1024)
#define NBLK    98              // NPAD/1024 blocks cover >= N_NODES

// ---------------- device scratch (no allocations allowed) ----------------
__device__ int   g_is64;
__device__ int   g_deg[NPAD];
__device__ int   g_cursor[NPAD];
__device__ int   g_bsum[128];
__device__ int   g_boff[128];
__device__ int   g_rowptr[NPAD + 1];
__device__ float g_invdeg[NPAD];
__device__ int   g_csr[E_MAX];
__device__ float g_agg[(size_t)N_NODES * 128];
__device__ float g_h1 [(size_t)N_NODES * 128];
__device__ float g_h2 [(size_t)N_NODES * 128];
__device__ __nv_bfloat16 g_xb[(size_t)N_NODES * 128];   // bf16 gather source
__device__ float g_G  [(size_t)N_NODES * 8];
__device__ float g_R  [(size_t)N_NODES * 8];

// ---------------- f32x2 packed-FMA helpers (sm_103a) ----------------
__device__ __forceinline__ unsigned long long pk2(float a, float b) {
    unsigned long long r;
    asm("mov.b64 %0, {%1, %2};" : "=l"(r) : "f"(a), "f"(b));
    return r;
}
__device__ __forceinline__ float2 upk2(unsigned long long v) {
    float2 r;
    asm("mov.b64 {%0, %1}, %2;" : "=f"(r.x), "=f"(r.y) : "l"(v));
    return r;
}
__device__ __forceinline__ void fma2(unsigned long long& d,
                                     unsigned long long a,
                                     unsigned long long b) {
    asm("fma.rn.f32x2 %0, %1, %2, %0;" : "+l"(d) : "l"(a), "l"(b));
}

// bf16x2 word -> two f32 via integer shifts (exact): lo<<16, hi&0xffff0000
__device__ __forceinline__ void bf2f(unsigned p, float& f0, float& f1) {
    unsigned u0 = p << 16;
    unsigned u1 = p & 0xffff0000u;
    f0 = __uint_as_float(u0);
    f1 = __uint_as_float(u1);
}

// ---------------- edge-index dtype detection (int32 vs int64) ----------------
__global__ void k_detect(const int* __restrict__ ei) {
    if (threadIdx.x == 0 && blockIdx.x == 0) {
        int acc = 0;
        for (int i = 0; i < 128; i++) acc |= ei[2 * i + 1];
        g_is64 = (acc == 0) ? 1 : 0;
    }
}

__device__ __forceinline__ int load_edge(const void* ei, int is64, size_t idx) {
    return is64 ? (int)((const long long*)ei)[idx] : ((const int*)ei)[idx];
}

// ---------------- CSR build ----------------
__global__ void k_zero() {
    int i = blockIdx.x * blockDim.x + threadIdx.x;
    if (i < NPAD) g_deg[i] = 0;
}

__global__ void k_hist(const void* __restrict__ ei, int E) {
    int is64 = g_is64;
    int stride = gridDim.x * blockDim.x;
    for (int i = blockIdx.x * blockDim.x + threadIdx.x; i < E; i += stride) {
        int d = load_edge(ei, is64, (size_t)E + i);
        atomicAdd(&g_deg[d], 1);
    }
}

__global__ void k_reduce() {
    __shared__ int ws[8];
    int t = threadIdx.x, lane = t & 31, warp = t >> 5;
    int4 v = ((const int4*)g_deg)[blockIdx.x * 256 + t];
    int s = v.x + v.y + v.z + v.w;
    #pragma unroll
    for (int off = 16; off; off >>= 1)
        s += __shfl_xor_sync(0xffffffffu, s, off);
    if (lane == 0) ws[warp] = s;
    __syncthreads();
    if (t == 0) {
        int tot = 0;
        #pragma unroll
        for (int i = 0; i < 8; i++) tot += ws[i];
        g_bsum[blockIdx.x] = tot;
    }
}

// parallel scan of the NBLK block sums (one 128-thread block)
__global__ void k_scanb(int E) {
    __shared__ int ws[4];
    int t = threadIdx.x;            // 0..127
    int lane = t & 31, warp = t >> 5;
    int v = (t < NBLK) ? g_bsum[t] : 0;
    int x = v;
    #pragma unroll
    for (int off = 1; off < 32; off <<= 1) {
        int y = __shfl_up_sync(0xffffffffu, x, off);
        if (lane >= off) x += y;
    }
    if (lane == 31) ws[warp] = x;
    __syncthreads();
    if (t == 0) {
        int r = 0;
        #pragma unroll
        for (int i = 0; i < 4; i++) { int tmp = ws[i]; ws[i] = r; r += tmp; }
    }
    __syncthreads();
    int excl = x - v + ws[warp];
    if (t < NBLK) g_boff[t] = excl;
    if (t == 0) g_rowptr[N_NODES] = E;
}

__global__ void k_scanw() {
    __shared__ int ws[8];
    int blk = blockIdx.x, t = threadIdx.x;
    int lane = t & 31, warp = t >> 5;
    int4 v = ((const int4*)g_deg)[blk * 256 + t];
    int tsum = v.x + v.y + v.z + v.w;
    int x = tsum;
    #pragma unroll
    for (int off = 1; off < 32; off <<= 1) {
        int y = __shfl_up_sync(0xffffffffu, x, off);
        if (lane >= off) x += y;
    }
    if (lane == 31) ws[warp] = x;
    __syncthreads();
    if (warp == 0) {
        int w = (lane < 8) ? ws[lane] : 0;
        #pragma unroll
        for (int off = 1; off < 8; off <<= 1) {
            int y = __shfl_up_sync(0xffffffffu, w, off);
            if (lane >= off) w += y;
        }
        if (lane < 8) ws[lane] = w;
    }
    __syncthreads();
    int excl = x - tsum + (warp ? ws[warp - 1] : 0) + g_boff[blk];
    int base = blk * 1024 + t * 4;
    int run = excl;
    g_rowptr[base + 0] = run; g_cursor[base + 0] = run;
    g_invdeg[base + 0] = 1.0f / (float)(v.x > 1 ? v.x : 1);
    run += v.x;
    g_rowptr[base + 1] = run; g_cursor[base + 1] = run;
    g_invdeg[base + 1] = 1.0f / (float)(v.y > 1 ? v.y : 1);
    run += v.y;
    g_rowptr[base + 2] = run; g_cursor[base + 2] = run;
    g_invdeg[base + 2] = 1.0f / (float)(v.z > 1 ? v.z : 1);
    run += v.z;
    g_rowptr[base + 3] = run; g_cursor[base + 3] = run;
    g_invdeg[base + 3] = 1.0f / (float)(v.w > 1 ? v.w : 1);
    run += v.w;
}

__global__ void k_scatter(const void* __restrict__ ei, int E) {
    int is64 = g_is64;
    int stride = gridDim.x * blockDim.x;
    for (int i = blockIdx.x * blockDim.x + threadIdx.x; i < E; i += stride) {
        int s = load_edge(ei, is64, i);
        int d = load_edge(ei, is64, (size_t)E + i);
        int pos = atomicAdd(&g_cursor[d], 1);
        g_csr[pos] = s;
    }
}

// ---------------- fp32 -> bf16 feature conversion ----------------
__global__ void k_cvt(const float* __restrict__ in) {
    size_t i = (size_t)blockIdx.x * 256 + threadIdx.x;   // float4 index
    float4 v = ((const float4*)in)[i];
    __nv_bfloat162 a = __floats2bfloat162_rn(v.x, v.y);
    __nv_bfloat162 b = __floats2bfloat162_rn(v.z, v.w);
    uint2 u;
    u.x = *(unsigned*)&a;
    u.y = *(unsigned*)&b;
    ((uint2*)g_xb)[i] = u;
}

// ---------------- mean aggregation from bf16 rows (warp per node, MLP 4) ------
// row = 128 bf16 = 256 bytes = 32 uint2; each of 32 lanes loads one uint2.
__global__ void k_agg_bf(float* __restrict__ o) {
    int gw = (blockIdx.x * blockDim.x + threadIdx.x) >> 5;   // node id
    int lane = threadIdx.x & 31;
    int beg = g_rowptr[gw], end = g_rowptr[gw + 1];
    const uint2* __restrict__ hb = (const uint2*)g_xb;       // 32 uint2 per row
    const int*  __restrict__ csr = g_csr;

    float a0 = 0.f, a1 = 0.f, a2 = 0.f, a3 = 0.f;
    int e = beg;
    for (; e + 4 <= end; e += 4) {
        int s0 = __ldg(csr + e);
        int s1 = __ldg(csr + e + 1);
        int s2 = __ldg(csr + e + 2);
        int s3 = __ldg(csr + e + 3);
        uint2 p0 = __ldg(hb + (size_t)s0 * 32 + lane);
        uint2 p1 = __ldg(hb + (size_t)s1 * 32 + lane);
        uint2 p2 = __ldg(hb + (size_t)s2 * 32 + lane);
        uint2 p3 = __ldg(hb + (size_t)s3 * 32 + lane);
        float f0, f1, f2, f3;
        bf2f(p0.x, f0, f1); bf2f(p0.y, f2, f3);
        a0 += f0; a1 += f1; a2 += f2; a3 += f3;
        bf2f(p1.x, f0, f1); bf2f(p1.y, f2, f3);
        a0 += f0; a1 += f1; a2 += f2; a3 += f3;
        bf2f(p2.x, f0, f1); bf2f(p2.y, f2, f3);
        a0 += f0; a1 += f1; a2 += f2; a3 += f3;
        bf2f(p3.x, f0, f1); bf2f(p3.y, f2, f3);
        a0 += f0; a1 += f1; a2 += f2; a3 += f3;
    }
    for (; e < end; e++) {
        int s0 = __ldg(csr + e);
        uint2 p0 = __ldg(hb + (size_t)s0 * 32 + lane);
        float f0, f1, f2, f3;
        bf2f(p0.x, f0, f1); bf2f(p0.y, f2, f3);
        a0 += f0; a1 += f1; a2 += f2; a3 += f3;
    }
    float d = g_invdeg[gw];
    float4 r;
    r.x = a0 * d; r.y = a1 * d; r.z = a2 * d; r.w = a3 * d;
    ((float4*)(o + (size_t)gw * 128))[lane] = r;
}

// NOTE on layout: lane reads bf16 elements [lane*4, lane*4+4) of the row, and
// the f32 accumulators map to output floats [lane*4, lane*4+4) — matches the
// float4 store below (same mapping as rounds 3/4).

// ---------------- fused GEMM: out = relu(agg@Wl^T + h@Wr^T + b) ----------------
// C[N,128] = A[N,256] * B[256,128],  A = [agg | h],  B[k][j] = Wl/Wr[j][k]
// BM=64, BN=128, BK=16, 256 threads, thread tile 8 rows x 4 cols, f32x2 FMAs.
// WB: also emit bf16 copy of the output into g_xb (gather source for next layer).
template <int RELU, int WB>
__global__ __launch_bounds__(256, 2)
void k_gemm(const float* __restrict__ Ag, const float* __restrict__ Hm,
            const float* __restrict__ Wl, const float* __restrict__ Wr,
            const float* __restrict__ bias, float* __restrict__ out)
{
    __shared__ __align__(16) float As[2][16][66];
    __shared__ __align__(16) float Bs[2][16][132];

    const int tid  = threadIdx.x;
    const int bm0  = blockIdx.x * 64;
    const int warp = tid >> 5, lane = tid & 31;
    const int row0 = (warp & 1) * 32 + (lane & 3) * 8;     // 0..56, step 8
    const int col0 = (warp >> 1) * 32 + (lane >> 2) * 4;   // 0..124, step 4
    const int arow = tid >> 2, akq = tid & 3;
    const int grow = bm0 + arow;
    const bool rok = grow < N_NODES;
    const int bj0 = tid >> 2, bkq = tid & 3;

    float4 ar, br0, br1;

#define GLOAD(kt) {                                                              \
    int gk = (kt) * 16 + akq * 4;                                                \
    if (rok) {                                                                   \
        const float* p = (gk < 128) ? (Ag + (size_t)grow * 128 + gk)             \
                                    : (Hm + (size_t)grow * 128 + (gk - 128));    \
        ar = *(const float4*)p;                                                  \
    } else ar = make_float4(0.f, 0.f, 0.f, 0.f);                                 \
    int gkb = (kt) * 16 + bkq * 4;                                               \
    { const float* p = (gkb < 128) ? (Wl + bj0 * 128 + gkb)                      \
                                   : (Wr + bj0 * 128 + (gkb - 128));             \
      br0 = *(const float4*)p; }                                                 \
    { int bj1 = bj0 + 64;                                                        \
      const float* p = (gkb < 128) ? (Wl + bj1 * 128 + gkb)                      \
                                   : (Wr + bj1 * 128 + (gkb - 128));             \
      br1 = *(const float4*)p; }                                                 \
}
#define SSTORE(s) {                                                              \
    As[s][akq * 4 + 0][arow] = ar.x; As[s][akq * 4 + 1][arow] = ar.y;            \
    As[s][akq * 4 + 2][arow] = ar.z; As[s][akq * 4 + 3][arow] = ar.w;            \
    Bs[s][bkq * 4 + 0][bj0] = br0.x; Bs[s][bkq * 4 + 1][bj0] = br0.y;            \
    Bs[s][bkq * 4 + 2][bj0] = br0.z; Bs[s][bkq * 4 + 3][bj0] = br0.w;            \
    Bs[s][bkq * 4 + 0][bj0 + 64] = br1.x; Bs[s][bkq * 4 + 1][bj0 + 64] = br1.y;  \
    Bs[s][bkq * 4 + 2][bj0 + 64] = br1.z; Bs[s][bkq * 4 + 3][bj0 + 64] = br1.w;  \
}

    unsigned long long acc[4][4];
    #pragma unroll
    for (int p = 0; p < 4; p++)
        #pragma unroll
        for (int j = 0; j < 4; j++) acc[p][j] = 0ull;

    GLOAD(0);
    SSTORE(0);
    __syncthreads();

    #pragma unroll 1
    for (int kt = 0; kt < 16; kt++) {
        int s = kt & 1;
        if (kt < 15) GLOAD(kt + 1);
        #pragma unroll
        for (int kk = 0; kk < 16; kk++) {
            unsigned long long a2[4];
            #pragma unroll
            for (int p = 0; p < 4; p++)
                a2[p] = *(const unsigned long long*)&As[s][kk][row0 + 2 * p];
            float4 b4 = *(const float4*)&Bs[s][kk][col0];
            unsigned long long bb0 = pk2(b4.x, b4.x);
            unsigned long long bb1 = pk2(b4.y, b4.y);
            unsigned long long bb2 = pk2(b4.z, b4.z);
            unsigned long long bb3 = pk2(b4.w, b4.w);
            #pragma unroll
            for (int p = 0; p < 4; p++) {
                fma2(acc[p][0], a2[p], bb0);
                fma2(acc[p][1], a2[p], bb1);
                fma2(acc[p][2], a2[p], bb2);
                fma2(acc[p][3], a2[p], bb3);
            }
        }
        if (kt < 15) { SSTORE(s ^ 1); __syncthreads(); }
    }

    float4 b4 = *(const float4*)&bias[col0];
    #pragma unroll
    for (int p = 0; p < 4; p++) {
        float2 c0 = upk2(acc[p][0]), c1 = upk2(acc[p][1]);
        float2 c2 = upk2(acc[p][2]), c3 = upk2(acc[p][3]);
        float4 lo = make_float4(c0.x + b4.x, c1.x + b4.y, c2.x + b4.z, c3.x + b4.w);
        float4 hi = make_float4(c0.y + b4.x, c1.y + b4.y, c2.y + b4.z, c3.y + b4.w);
        if (RELU) {
            lo.x = fmaxf(lo.x, 0.f); lo.y = fmaxf(lo.y, 0.f);
            lo.z = fmaxf(lo.z, 0.f); lo.w = fmaxf(lo.w, 0.f);
            hi.x = fmaxf(hi.x, 0.f); hi.y = fmaxf(hi.y, 0.f);
            hi.z = fmaxf(hi.z, 0.f); hi.w = fmaxf(hi.w, 0.f);
        }
        int r0 = bm0 + row0 + 2 * p;
        if (r0 < N_NODES) {
            *(float4*)&out[(size_t)r0 * 128 + col0] = lo;
            if (WB) {
                __nv_bfloat162 q0 = __floats2bfloat162_rn(lo.x, lo.y);
                __nv_bfloat162 q1 = __floats2bfloat162_rn(lo.z, lo.w);
                uint2 u; u.x = *(unsigned*)&q0; u.y = *(unsigned*)&q1;
                *(uint2*)&g_xb[(size_t)r0 * 128 + col0] = u;
            }
        }
        if (r0 + 1 < N_NODES) {
            *(float4*)&out[(size_t)(r0 + 1) * 128 + col0] = hi;
            if (WB) {
                __nv_bfloat162 q0 = __floats2bfloat162_rn(hi.x, hi.y);
                __nv_bfloat162 q1 = __floats2bfloat162_rn(hi.z, hi.w);
                uint2 u; u.x = *(unsigned*)&q0; u.y = *(unsigned*)&q1;
                *(uint2*)&g_xb[(size_t)(r0 + 1) * 128 + col0] = u;
            }
        }
    }
#undef GLOAD
#undef SSTORE
}

// ---------------- layer-3 thin projections: G = H2@Wl3^T, R = H2@Wr3^T + b3 ----
__global__ void k_gemm3(const float* __restrict__ H,
                        const float* __restrict__ Wl, const float* __restrict__ Wr,
                        const float* __restrict__ b) {
    __shared__ __align__(16) float sW[12 * 128];
    __shared__ float sb[8];
    int t = threadIdx.x;
    for (int i = t; i < 1536; i += 256) sW[i] = (i < 768) ? Wl[i] : Wr[i - 768];
    if (t < 6) sb[t] = b[t];
    __syncthreads();
    int lane = t & 31, warp = t >> 5;
    int node = blockIdx.x * 8 + warp;
    float4 h4 = ((const float4*)(H + (size_t)node * 128))[lane];
    float r[12];
    #pragma unroll
    for (int j = 0; j < 12; j++) {
        float4 w = ((const float4*)(sW + j * 128))[lane];
        r[j] = h4.x * w.x + h4.y * w.y + h4.z * w.z + h4.w * w.w;
    }
    #pragma unroll
    for (int j = 0; j < 12; j++) {
        #pragma unroll
        for (int off = 16; off; off >>= 1)
            r[j] += __shfl_xor_sync(0xffffffffu, r[j], off);
    }
    if (lane == 0) {
        #pragma unroll
        for (int j = 0; j < 6; j++) {
            g_G[(size_t)node * 8 + j] = r[j];
            g_R[(size_t)node * 8 + j] = r[j + 6] + sb[j];
        }
    }
}

// ---------------- final: out = invdeg * sum_e G[src] + R  (6-dim aggregation) ----
__global__ void k_final(float* __restrict__ out) {
    int gw = (blockIdx.x * blockDim.x + threadIdx.x) >> 5;   // node
    int lane = threadIdx.x & 31;
    int sub = lane >> 3, c = lane & 7;                       // 4 neighbors x 8 lanes
    int beg = g_rowptr[gw], end = g_rowptr[gw + 1];
    float acc = 0.f;
    for (int e = beg + sub; e < end; e += 4) {
        int s = g_csr[e];
        acc += g_G[(size_t)s * 8 + c];
    }
    acc += __shfl_xor_sync(0xffffffffu, acc, 8);
    acc += __shfl_xor_sync(0xffffffffu, acc, 16);
    if (lane < 6)
        out[(size_t)gw * 6 + lane] = acc * g_invdeg[gw] + g_R[(size_t)gw * 8 + lane];
}

// ---------------- host launcher ----------------
extern "C" void kernel_launch(void* const* d_in, const int* in_sizes, int n_in,
                              void* d_out, int out_size) {
    const float* x   = (const float*)d_in[0];
    const void*  ei  = d_in[1];
    const float *Wl1 = (const float*)d_in[2], *Wr1 = (const float*)d_in[3], *b1 = (const float*)d_in[4];
    const float *Wl2 = (const float*)d_in[5], *Wr2 = (const float*)d_in[6], *b2 = (const float*)d_in[7];
    const float *Wl3 = (const float*)d_in[8], *Wr3 = (const float*)d_in[9], *b3 = (const float*)d_in[10];
    float* out = (float*)d_out;
    int E = in_sizes[1] / 2;

    float *agg, *h1, *h2;
    cudaGetSymbolAddress((void**)&agg, g_agg);
    cudaGetSymbolAddress((void**)&h1,  g_h1);
    cudaGetSymbolAddress((void**)&h2,  g_h2);

    // CSR build (counting sort by destination)
    k_detect<<<1, 32>>>((const int*)ei);
    k_zero<<<NPAD / 256, 256>>>();
    k_hist<<<2560, 256>>>(ei, E);
    k_reduce<<<NBLK, 256>>>();
    k_scanb<<<1, 128>>>(E);
    k_scanw<<<NBLK, 256>>>();
    k_scatter<<<2560, 256>>>(ei, E);
    k_cvt<<<(N_NODES * 128 / 4) / 256, 256>>>(x);   // x -> bf16

    // layer 1 (gemm epilogue emits bf16 h1 into g_xb)
    k_agg_bf<<<N_NODES / 8, 256>>>(agg);
    k_gemm<1, 1><<<(N_NODES + 63) / 64, 256>>>(agg, x, Wl1, Wr1, b1, h1);
    // layer 2
    k_agg_bf<<<N_NODES / 8, 256>>>(agg);
    k_gemm<1, 0><<<(N_NODES + 63) / 64, 256>>>(agg, h1, Wl2, Wr2, b2, h2);
    // layer 3 (project to 6 dims first, then aggregate cheap)
    k_gemm3<<<N_NODES / 8, 256>>>(h2, Wl3, Wr3, b3);
    k_final<<<N_NODES / 8, 256>>>(out);
}